// round 3
// baseline (speedup 1.0000x reference)
#include <cuda_runtime.h>
#include <math.h>

#define NN 8192
#define DD 1024

// Scratch (allocation-free rule: __device__ globals)
__device__ float g_emb[(size_t)NN * DD];   // normalized embeddings, 32 MB
__device__ float g_rowloss[NN];

// ---------------------------------------------------------------------------
// Kernel 1: L2-normalize each row. One block per row, 256 threads, float4.
// ---------------------------------------------------------------------------
__global__ void __launch_bounds__(256) norm_kernel(const float* __restrict__ in) {
    int row = blockIdx.x;
    const float4* r = (const float4*)(in + (size_t)row * DD);
    float4 v = r[threadIdx.x];              // 256 threads * 4 floats = 1024
    float s = v.x * v.x + v.y * v.y + v.z * v.z + v.w * v.w;
    #pragma unroll
    for (int o = 16; o > 0; o >>= 1) s += __shfl_xor_sync(0xffffffffu, s, o);
    __shared__ float ws[8];
    int lane = threadIdx.x & 31, w = threadIdx.x >> 5;
    if (lane == 0) ws[w] = s;
    __syncthreads();
    if (threadIdx.x == 0) {
        float t = 0.f;
        #pragma unroll
        for (int i = 0; i < 8; i++) t += ws[i];
        ws[0] = 1.0f / fmaxf(sqrtf(t), 1e-12f);
    }
    __syncthreads();
    float inv = ws[0];
    float4 o;
    o.x = v.x * inv; o.y = v.y * inv; o.z = v.z * inv; o.w = v.w * inv;
    ((float4*)(g_emb + (size_t)row * DD))[threadIdx.x] = o;
}

// ---------------------------------------------------------------------------
// Kernel 2: fused sim-GEMM + exp + masked row sums.
// Block: 256 threads (16x16), BM=BN=64, BK=16, 4x4 register tile per thread.
// Each block owns 64 rows and loops over all 128 column tiles; sim tile is
// consumed in registers (never hits memory).
// NOTE: labels are int32 (JAX x64 disabled -> jnp.int64 silently lowers to
// int32; reading as int64 was the round-2 correctness bug).
// ---------------------------------------------------------------------------
__global__ void __launch_bounds__(256) sim_kernel(const int* __restrict__ labels) {
    __shared__ float As[16][64];
    __shared__ float Bs[16][64];
    __shared__ int colLab[64];

    const int tid = threadIdx.x;
    const int tx = tid & 15, ty = tid >> 4;
    const int rowBase = blockIdx.x * 64;

    int rlab[4];
    #pragma unroll
    for (int i = 0; i < 4; i++) rlab[i] = labels[rowBase + ty * 4 + i];

    float sumExp[4] = {0.f, 0.f, 0.f, 0.f};
    float posSum[4] = {0.f, 0.f, 0.f, 0.f};

    const int lr = tid >> 2;            // 0..63 (tile row for loads)
    const int lc = (tid & 3) * 4;       // 0,4,8,12 (tile col group)
    const float* Aptr = g_emb + (size_t)(rowBase + lr) * DD + lc;

    const float invT = 1.0f / 0.07f;

    for (int ct = 0; ct < NN / 64; ++ct) {
        const int colBase = ct * 64;
        __syncthreads();                 // prior epilogue finished reading colLab
        if (tid < 64) colLab[tid] = labels[colBase + tid];
        const float* Bptr = g_emb + (size_t)(colBase + lr) * DD + lc;

        float acc[4][4];
        #pragma unroll
        for (int i = 0; i < 4; i++)
            #pragma unroll
            for (int j = 0; j < 4; j++) acc[i][j] = 0.f;

        for (int kt = 0; kt < DD; kt += 16) {
            float4 a = *(const float4*)(Aptr + kt);
            float4 b = *(const float4*)(Bptr + kt);
            As[lc + 0][lr] = a.x; As[lc + 1][lr] = a.y;
            As[lc + 2][lr] = a.z; As[lc + 3][lr] = a.w;
            Bs[lc + 0][lr] = b.x; Bs[lc + 1][lr] = b.y;
            Bs[lc + 2][lr] = b.z; Bs[lc + 3][lr] = b.w;
            __syncthreads();
            #pragma unroll
            for (int k = 0; k < 16; k++) {
                float4 av = *(const float4*)&As[k][ty * 4];
                float4 bv = *(const float4*)&Bs[k][tx * 4];
                float ar[4] = {av.x, av.y, av.z, av.w};
                float br[4] = {bv.x, bv.y, bv.z, bv.w};
                #pragma unroll
                for (int i = 0; i < 4; i++)
                    #pragma unroll
                    for (int j = 0; j < 4; j++)
                        acc[i][j] = fmaf(ar[i], br[j], acc[i][j]);
            }
            __syncthreads();
        }

        // Epilogue: exp + masked accumulation (sim tile stays in registers)
        #pragma unroll
        for (int i = 0; i < 4; i++) {
            const int gi = rowBase + ty * 4 + i;
            #pragma unroll
            for (int j = 0; j < 4; j++) {
                const int gj = colBase + tx * 4 + j;
                float e = __expf(acc[i][j] * invT);
                sumExp[i] += e;
                if (colLab[tx * 4 + j] == rlab[i] && gi != gj) posSum[i] += e;
            }
        }
    }

    // Reduce across the 16 tx-threads holding the same rows (butterfly over
    // lane bits 0..3 — tx maps to the low 4 lane bits).
    #pragma unroll
    for (int i = 0; i < 4; i++) {
        #pragma unroll
        for (int o = 1; o < 16; o <<= 1) {
            sumExp[i] += __shfl_xor_sync(0xffffffffu, sumExp[i], o);
            posSum[i] += __shfl_xor_sync(0xffffffffu, posSum[i], o);
        }
    }
    if (tx == 0) {
        #pragma unroll
        for (int i = 0; i < 4; i++)
            g_rowloss[rowBase + ty * 4 + i] = logf(sumExp[i]) - logf(posSum[i]);
    }
}

// ---------------------------------------------------------------------------
// Kernel 3: mean over row losses.
// ---------------------------------------------------------------------------
__global__ void __launch_bounds__(256) reduce_kernel(float* __restrict__ out) {
    float s = 0.f;
    for (int i = threadIdx.x; i < NN; i += 256) s += g_rowloss[i];
    #pragma unroll
    for (int o = 16; o > 0; o >>= 1) s += __shfl_xor_sync(0xffffffffu, s, o);
    __shared__ float ws[8];
    int lane = threadIdx.x & 31, w = threadIdx.x >> 5;
    if (lane == 0) ws[w] = s;
    __syncthreads();
    if (threadIdx.x == 0) {
        float t = 0.f;
        #pragma unroll
        for (int i = 0; i < 8; i++) t += ws[i];
        out[0] = t / (float)NN;
    }
}

extern "C" void kernel_launch(void* const* d_in, const int* in_sizes, int n_in,
                              void* d_out, int out_size) {
    const float* emb = (const float*)d_in[0];
    const int* labels = (const int*)d_in[1];
    norm_kernel<<<NN, 256>>>(emb);
    sim_kernel<<<NN / 64, 256>>>(labels);
    reduce_kernel<<<1, 256>>>((float*)d_out);
}

// round 6
// speedup vs baseline: 11.2528x; 11.2528x over previous
#include <cuda_runtime.h>
#include <cuda_bf16.h>
#include <math.h>
#include <stdint.h>

#define NN 8192
#define DD 1024

// ---------------- scratch (allocation-free rule) ----------------
__device__ __nv_bfloat16 g_embh[(size_t)NN * DD];  // normalized emb, bf16, 16MB
__device__ float g_sumPart[2 * NN];
__device__ float g_posPart[2 * NN];

// ---------------- geometry ----------------
#define BM 128
#define BN 128
#define BK 64
#define STAGES 3
#define KSTEPS (DD / BK)          // 16
#define COLT 32                   // column tiles per CTA (4096/128)
#define ROWELEMS 72               // smem row stride in bf16 (144 B: 128B data + 16B pad)
#define ROWBYTES 144
#define STAGE_BYTES (128 * ROWBYTES)   // 18432

// dynamic smem layout (bytes)
#define SM_COLLAB   0                         // int[128]
#define SM_SUMBUF   512                       // float[2][128]
#define SM_POSBUF   1536                      // float[2][128]
#define SM_A(s)     (4096 + (s) * STAGE_BYTES)
#define SM_B(s)     (4096 + STAGES * STAGE_BYTES + (s) * STAGE_BYTES)
#define SMEM_TOTAL  (4096 + 2 * STAGES * STAGE_BYTES)   // 114688

// ---------------- PTX helpers ----------------
#define CP_ASYNC16(dst_u32, src_ptr) \
    asm volatile("cp.async.cg.shared.global [%0], [%1], 16;" \
                 :: "r"(dst_u32), "l"(src_ptr) : "memory")
#define CP_COMMIT() asm volatile("cp.async.commit_group;" ::: "memory")

#define LDSM_X4(r0, r1, r2, r3, addr) \
    asm volatile("ldmatrix.sync.aligned.m8n8.x4.shared.b16 {%0,%1,%2,%3}, [%4];" \
                 : "=r"(r0), "=r"(r1), "=r"(r2), "=r"(r3) : "r"(addr))

#define MMA16816(d, a, b) \
    asm volatile("mma.sync.aligned.m16n8k16.row.col.f32.bf16.bf16.f32 " \
                 "{%0,%1,%2,%3}, {%4,%5,%6,%7}, {%8,%9}, {%0,%1,%2,%3};" \
                 : "+f"((d)[0]), "+f"((d)[1]), "+f"((d)[2]), "+f"((d)[3]) \
                 : "r"((a)[0]), "r"((a)[1]), "r"((a)[2]), "r"((a)[3]), \
                   "r"((b)[0]), "r"((b)[1]))

// ---------------------------------------------------------------------------
// Kernel 1: L2-normalize rows -> bf16
// ---------------------------------------------------------------------------
__global__ void __launch_bounds__(256) norm_kernel(const float* __restrict__ in) {
    int row = blockIdx.x;
    float4 v = ((const float4*)(in + (size_t)row * DD))[threadIdx.x];
    float s = v.x * v.x + v.y * v.y + v.z * v.z + v.w * v.w;
    #pragma unroll
    for (int o = 16; o > 0; o >>= 1) s += __shfl_xor_sync(0xffffffffu, s, o);
    __shared__ float ws[8];
    int lane = threadIdx.x & 31, w = threadIdx.x >> 5;
    if (lane == 0) ws[w] = s;
    __syncthreads();
    if (threadIdx.x == 0) {
        float t = 0.f;
        #pragma unroll
        for (int i = 0; i < 8; i++) t += ws[i];
        ws[0] = 1.0f / fmaxf(sqrtf(t), 1e-12f);
    }
    __syncthreads();
    float inv = ws[0];
    __nv_bfloat16 o[4];
    o[0] = __float2bfloat16(v.x * inv);
    o[1] = __float2bfloat16(v.y * inv);
    o[2] = __float2bfloat16(v.z * inv);
    o[3] = __float2bfloat16(v.w * inv);
    *(uint2*)(g_embh + (size_t)row * DD + threadIdx.x * 4) = *(uint2*)o;
}

// ---------------------------------------------------------------------------
// Kernel 2: bf16 mma.sync fused sim-GEMM + exp + masked row sums.
// Grid 128 = 64 row tiles x 2 col halves. 256 threads = 8 warps (4x2),
// warp tile 32x64, m16n8k16, fp32 accum. 3-stage cp.async pipeline.
// ---------------------------------------------------------------------------
__global__ void __launch_bounds__(256, 1) sim_kernel(const int* __restrict__ labels) {
    extern __shared__ char smem[];
    const uint32_t sb = (uint32_t)__cvta_generic_to_shared(smem);
    int* colLab = (int*)(smem + SM_COLLAB);
    float* sumBuf = (float*)(smem + SM_SUMBUF);
    float* posBuf = (float*)(smem + SM_POSBUF);

    const int tid = threadIdx.x;
    const int lane = tid & 31;
    const int wid = tid >> 5;
    const int wr = wid >> 1;          // 0..3 (row group of 32)
    const int wc = wid & 1;           // 0..1 (col group of 64)
    const int rowBase = (blockIdx.x >> 1) * BM;
    const int colHalf = blockIdx.x & 1;
    const int colHalfBase = colHalf * 4096;

    // per-thread rows (4): mf in {0,1}, h in {0,1}
    int rlRows[4], rlab[4];
    #pragma unroll
    for (int mf = 0; mf < 2; mf++)
        #pragma unroll
        for (int h = 0; h < 2; h++) {
            int rl = wr * 32 + mf * 16 + (lane >> 2) + h * 8;
            rlRows[mf * 2 + h] = rl;
            rlab[mf * 2 + h] = labels[rowBase + rl];
        }

    const float invT = 1.0f / 0.07f;
    const float diagE = expf(invT);
    float sumL[4] = {0.f, 0.f, 0.f, 0.f};
    float posL[4] = {0.f, 0.f, 0.f, 0.f};

    // cp.async thread mapping: 4 chunks of A + 4 chunks of B per thread/stage
    const int ldRow = tid >> 3;         // base rows 0..31 step 32
    const int ldChunk = tid & 7;        // 16B chunk within 128B row

    for (int ct = 0; ct < COLT; ct++) {
        const int colBase = colHalfBase + ct * BN;
        __syncthreads();   // prior epilogue finished reading colLab; buffers free
        if (tid < BN) colLab[tid] = labels[colBase + tid];

        // ---- preload stages 0,1 ----
        #pragma unroll
        for (int ps = 0; ps < 2; ps++) {
            const int kOff = ps * BK;
            #pragma unroll
            for (int i = 0; i < 4; i++) {
                const int row = ldRow + i * 32;
                const uint32_t dst = sb + SM_A(ps) + row * ROWBYTES + ldChunk * 16;
                CP_ASYNC16(dst, g_embh + (size_t)(rowBase + row) * DD + kOff + ldChunk * 8);
            }
            #pragma unroll
            for (int i = 0; i < 4; i++) {
                const int row = ldRow + i * 32;
                const uint32_t dst = sb + SM_B(ps) + row * ROWBYTES + ldChunk * 16;
                CP_ASYNC16(dst, g_embh + (size_t)(colBase + row) * DD + kOff + ldChunk * 8);
            }
            CP_COMMIT();
        }

        float acc[2][8][4];
        #pragma unroll
        for (int mf = 0; mf < 2; mf++)
            #pragma unroll
            for (int nf = 0; nf < 8; nf++)
                #pragma unroll
                for (int e = 0; e < 4; e++) acc[mf][nf][e] = 0.f;

        #pragma unroll 1
        for (int ks = 0; ks < KSTEPS; ks++) {
            // issue load for ks+2
            if (ks < KSTEPS - 2) {
                const int s2 = (ks + 2) % STAGES;
                const int kOff = (ks + 2) * BK;
                #pragma unroll
                for (int i = 0; i < 4; i++) {
                    const int row = ldRow + i * 32;
                    const uint32_t dst = sb + SM_A(s2) + row * ROWBYTES + ldChunk * 16;
                    CP_ASYNC16(dst, g_embh + (size_t)(rowBase + row) * DD + kOff + ldChunk * 8);
                }
                #pragma unroll
                for (int i = 0; i < 4; i++) {
                    const int row = ldRow + i * 32;
                    const uint32_t dst = sb + SM_B(s2) + row * ROWBYTES + ldChunk * 16;
                    CP_ASYNC16(dst, g_embh + (size_t)(colBase + row) * DD + kOff + ldChunk * 8);
                }
                CP_COMMIT();
                asm volatile("cp.async.wait_group 2;" ::: "memory");
            } else if (ks == KSTEPS - 2) {
                asm volatile("cp.async.wait_group 1;" ::: "memory");
            } else {
                asm volatile("cp.async.wait_group 0;" ::: "memory");
            }
            __syncthreads();

            const int buf = ks % STAGES;
            const uint32_t aBase = sb + SM_A(buf);
            const uint32_t bBase = sb + SM_B(buf);
            #pragma unroll
            for (int k16 = 0; k16 < BK / 16; k16++) {
                const uint32_t colByte = k16 * 32 + (lane >> 4) * 16;
                uint32_t a[2][4], b[8][2];
                #pragma unroll
                for (int mf = 0; mf < 2; mf++) {
                    const uint32_t addr =
                        aBase + (wr * 32 + mf * 16 + (lane & 15)) * ROWBYTES + colByte;
                    LDSM_X4(a[mf][0], a[mf][1], a[mf][2], a[mf][3], addr);
                }
                #pragma unroll
                for (int nb = 0; nb < 4; nb++) {
                    uint32_t r0, r1, r2, r3;
                    const uint32_t addr =
                        bBase + (wc * 64 + nb * 16 + (lane & 15)) * ROWBYTES + colByte;
                    LDSM_X4(r0, r1, r2, r3, addr);
                    b[nb * 2][0] = r0; b[nb * 2][1] = r2;
                    b[nb * 2 + 1][0] = r1; b[nb * 2 + 1][1] = r3;
                }
                #pragma unroll
                for (int mf = 0; mf < 2; mf++)
                    #pragma unroll
                    for (int nf = 0; nf < 8; nf++)
                        MMA16816(acc[mf][nf], a[mf], b[nf]);
            }
            __syncthreads();
        }

        // ---- epilogue: exp + masked accumulation from registers ----
        #pragma unroll
        for (int mf = 0; mf < 2; mf++) {
            #pragma unroll
            for (int nf = 0; nf < 8; nf++) {
                #pragma unroll
                for (int e = 0; e < 4; e++) {
                    const int h = e >> 1;
                    const int li = mf * 2 + h;
                    const int cl = wc * 64 + nf * 8 + (lane & 3) * 2 + (e & 1);
                    const int cg = colBase + cl;
                    const int rg = rowBase + rlRows[li];
                    const float ev = __expf(acc[mf][nf][e] * invT);
                    const bool diag = (cg == rg);
                    sumL[li] += diag ? diagE : ev;
                    if (!diag && colLab[cl] == rlab[li]) posL[li] += ev;
                }
            }
        }
    }

    // ---- reduce the 4 col-threads per row group, then cross-warp via smem ----
    #pragma unroll
    for (int li = 0; li < 4; li++) {
        float s = sumL[li], p = posL[li];
        s += __shfl_xor_sync(0xffffffffu, s, 1);
        s += __shfl_xor_sync(0xffffffffu, s, 2);
        p += __shfl_xor_sync(0xffffffffu, p, 1);
        p += __shfl_xor_sync(0xffffffffu, p, 2);
        if ((lane & 3) == 0) {
            sumBuf[wc * 128 + rlRows[li]] = s;
            posBuf[wc * 128 + rlRows[li]] = p;
        }
    }
    __syncthreads();
    if (tid < BM) {
        g_sumPart[colHalf * NN + rowBase + tid] = sumBuf[tid] + sumBuf[128 + tid];
        g_posPart[colHalf * NN + rowBase + tid] = posBuf[tid] + posBuf[128 + tid];
    }
}

// ---------------------------------------------------------------------------
// Kernel 3: per-row loss + mean
// ---------------------------------------------------------------------------
__global__ void __launch_bounds__(1024) reduce_kernel(float* __restrict__ out) {
    float acc = 0.f;
    for (int i = threadIdx.x; i < NN; i += 1024) {
        float s = g_sumPart[i] + g_sumPart[NN + i];
        float p = g_posPart[i] + g_posPart[NN + i];
        acc += logf(s) - logf(p);
    }
    #pragma unroll
    for (int o = 16; o > 0; o >>= 1) acc += __shfl_xor_sync(0xffffffffu, acc, o);
    __shared__ float ws[32];
    int lane = threadIdx.x & 31, w = threadIdx.x >> 5;
    if (lane == 0) ws[w] = acc;
    __syncthreads();
    if (threadIdx.x == 0) {
        float t = 0.f;
        #pragma unroll
        for (int i = 0; i < 32; i++) t += ws[i];
        out[0] = t / (float)NN;
    }
}

extern "C" void kernel_launch(void* const* d_in, const int* in_sizes, int n_in,
                              void* d_out, int out_size) {
    const float* emb = (const float*)d_in[0];
    const int* labels = (const int*)d_in[1];
    cudaFuncSetAttribute(sim_kernel, cudaFuncAttributeMaxDynamicSharedMemorySize, SMEM_TOTAL);
    norm_kernel<<<NN, 256>>>(emb);
    sim_kernel<<<128, 256, SMEM_TOTAL>>>(labels);
    reduce_kernel<<<1, 1024>>>((float*)d_out);
}